// round 1
// baseline (speedup 1.0000x reference)
#include <cuda_runtime.h>

// ---------------------------------------------------------------------------
// encoderOnlyComplex: VoxelMorph-style registration network, fp32 baseline.
// Round 0: correctness-first direct implementation, all fp32, single stream,
// graph-capturable (only kernel launches + D2D memcpyAsync, no allocations).
// ---------------------------------------------------------------------------

#define V64 262144            // 64^3
#define PYR_TOT 299584        // 64^3+32^3+16^3+8^3+4^3

// ---------------- static scratch (allocation-free rule) --------------------
__device__ float g_bufA[2 * 32 * V64];   // encoder ping
__device__ float g_bufB[2 * 32 * V64];   // encoder pong
__device__ float g_xs[16 * PYR_TOT];     // x feature pyramid
__device__ float g_ys[16 * PYR_TOT];     // y feature pyramid
__device__ float g_warp16[16 * V64];     // warped xi
__device__ float g_cat[32 * V64];        // concat(yi+xi, yi-xi)
__device__ float g_feat1[32 * V64];
__device__ float g_feat2[27 * V64];
__device__ float g_flow[3 * V64];
__device__ float g_vecA[3 * V64];
__device__ float g_vecB[3 * V64];
__device__ float g_up[3 * V64];
__device__ float g_mu[64];
__device__ float g_rsig[64];

// ---------------------------------------------------------------------------
// Direct 3x3x3 conv, pad 1. One thread per output voxel of one (n, co).
// Weights for this co staged in shared memory. Optional fused ReLU.
// in:  (N, Cin, D,D,D)   w: (Cout, Cin, 3,3,3)   out: (N, Cout, D,D,D)
// grid = (ceil(vox/256), Cout, N)
// ---------------------------------------------------------------------------
__global__ void conv3x3x3(const float* __restrict__ in, const float* __restrict__ w,
                          const float* __restrict__ bias, float* __restrict__ out,
                          int Cin, int D, int do_relu) {
    const int vox = D * D * D;
    const int co = blockIdx.y;
    const int n  = blockIdx.z;
    extern __shared__ float ws[];
    const int nw = Cin * 27;
    for (int i = threadIdx.x; i < nw; i += blockDim.x)
        ws[i] = w[(size_t)co * nw + i];
    __syncthreads();

    int idx = blockIdx.x * blockDim.x + threadIdx.x;
    if (idx >= vox) return;
    int x = idx % D;
    int t = idx / D;
    int y = t % D;
    int z = t / D;

    const float* inb = in + (size_t)n * Cin * vox;
    float acc = bias[co];
    for (int ci = 0; ci < Cin; ci++) {
        const float* ip = inb + (size_t)ci * vox;
        const float* wp = ws + ci * 27;
        #pragma unroll
        for (int kz = 0; kz < 3; kz++) {
            int zz = z + kz - 1;
            if ((unsigned)zz >= (unsigned)D) continue;
            #pragma unroll
            for (int ky = 0; ky < 3; ky++) {
                int yy = y + ky - 1;
                if ((unsigned)yy >= (unsigned)D) continue;
                const float* row = ip + ((size_t)zz * D + yy) * D;
                #pragma unroll
                for (int kx = 0; kx < 3; kx++) {
                    int xx = x + kx - 1;
                    if ((unsigned)xx >= (unsigned)D) continue;
                    acc += row[xx] * wp[kz * 9 + ky * 3 + kx];
                }
            }
        }
    }
    if (do_relu) acc = fmaxf(acc, 0.f);
    out[((size_t)n * gridDim.y + co) * vox + idx] = acc;
}

// ---------------------------------------------------------------------------
// Instance-norm statistics: one block per (n,c).
// ---------------------------------------------------------------------------
__global__ void inorm_stats(const float* __restrict__ in, float* __restrict__ mu,
                            float* __restrict__ rsig, int vox) {
    const int nc = blockIdx.x;
    const float* p = in + (size_t)nc * vox;
    float s = 0.f, s2 = 0.f;
    for (int i = threadIdx.x; i < vox; i += blockDim.x) {
        float v = p[i];
        s += v;
        s2 += v * v;
    }
    __shared__ float sh[256], sh2[256];
    sh[threadIdx.x] = s;
    sh2[threadIdx.x] = s2;
    __syncthreads();
    for (int o = 128; o > 0; o >>= 1) {
        if (threadIdx.x < o) {
            sh[threadIdx.x]  += sh[threadIdx.x + o];
            sh2[threadIdx.x] += sh2[threadIdx.x + o];
        }
        __syncthreads();
    }
    if (threadIdx.x == 0) {
        float m = sh[0] / (float)vox;
        float var = sh2[0] / (float)vox - m * m;
        mu[nc] = m;
        rsig[nc] = rsqrtf(var + 1e-5f);
    }
}

// Normalize + PReLU, in place. nc = idx / vox.
__global__ void norm_prelu(float* __restrict__ data, const float* __restrict__ mu,
                           const float* __restrict__ rsig, const float* __restrict__ alpha,
                           int vox, int total) {
    int idx = blockIdx.x * blockDim.x + threadIdx.x;
    if (idx >= total) return;
    int nc = idx / vox;
    float v = (data[idx] - mu[nc]) * rsig[nc];
    float a = *alpha;
    data[idx] = v >= 0.f ? v : a * v;
}

// ---------------------------------------------------------------------------
// Trilinear resize (align-corners style, matching reference's per-axis
// linear interp with i0 = clip(floor(c),0,in-2), t = c - i0). gain applied.
// ---------------------------------------------------------------------------
__global__ void resize_tri(const float* __restrict__ in, float* __restrict__ out,
                           int C, int inD, int outD, float gain) {
    const int ov = outD * outD * outD;
    const int iv = inD * inD * inD;
    int idx = blockIdx.x * blockDim.x + threadIdx.x;
    int total = C * ov;
    if (idx >= total) return;
    int p = idx % ov;
    int c = idx / ov;
    int x = p % outD;
    int t = p / outD;
    int y = t % outD;
    int z = t / outD;

    float r = (float)(inD - 1) / (float)(outD - 1);
    float cz = z * r, cy = y * r, cx = x * r;
    int z0 = min(max((int)floorf(cz), 0), inD - 2);
    int y0 = min(max((int)floorf(cy), 0), inD - 2);
    int x0 = min(max((int)floorf(cx), 0), inD - 2);
    float tz = cz - (float)z0;
    float ty = cy - (float)y0;
    float tx = cx - (float)x0;

    const float* ip = in + (size_t)c * iv;
    size_t b000 = ((size_t)z0 * inD + y0) * inD + x0;
    size_t sy = inD, sz = (size_t)inD * inD;
    float v000 = ip[b000],          v001 = ip[b000 + 1];
    float v010 = ip[b000 + sy],     v011 = ip[b000 + sy + 1];
    float v100 = ip[b000 + sz],     v101 = ip[b000 + sz + 1];
    float v110 = ip[b000 + sz + sy],v111 = ip[b000 + sz + sy + 1];

    float c00 = v000 * (1.f - tx) + v001 * tx;
    float c01 = v010 * (1.f - tx) + v011 * tx;
    float c10 = v100 * (1.f - tx) + v101 * tx;
    float c11 = v110 * (1.f - tx) + v111 * tx;
    float c0 = c00 * (1.f - ty) + c01 * ty;
    float c1 = c10 * (1.f - ty) + c11 * ty;
    out[idx] = gain * (c0 * (1.f - tz) + c1 * tz);
}

// ---------------------------------------------------------------------------
// Generic warp: out[c,p] = (addend ? addend[c,p] : 0) + sample(src[c], grid+flow[:,p])
// Zero-padding grid-sample semantics (invalid corners get weight 0, indices
// clamped), matching the reference exactly.
//   plain warp     : addend = nullptr
//   vecint step    : src = flow = addend = vec, out = other buffer
//   flow compose   : src = up, flow = addend = out = vec (in-place safe:
//                    each thread only reads/writes its own idx of vec)
// ---------------------------------------------------------------------------
__global__ void warp_generic(const float* __restrict__ src, const float* __restrict__ flow,
                             const float* __restrict__ addend, float* __restrict__ out,
                             int C, int D) {
    const int vox = D * D * D;
    int idx = blockIdx.x * blockDim.x + threadIdx.x;
    if (idx >= vox) return;
    int x = idx % D;
    int t = idx / D;
    int y = t % D;
    int z = t / D;

    float zz = (float)z + flow[idx];
    float yy = (float)y + flow[vox + idx];
    float xx = (float)x + flow[2 * vox + idx];

    float zf = floorf(zz), yf = floorf(yy), xf = floorf(xx);
    int z0 = (int)zf, y0 = (int)yf, x0 = (int)xf;
    float wz = zz - zf, wy = yy - yf, wx = xx - xf;

    int offs[8];
    float wts[8];
    int k = 0;
    #pragma unroll
    for (int dz = 0; dz < 2; dz++) {
        int zi = z0 + dz;
        bool vz = (zi >= 0) && (zi < D);
        int zc = min(max(zi, 0), D - 1);
        float fz = dz ? wz : 1.f - wz;
        #pragma unroll
        for (int dy = 0; dy < 2; dy++) {
            int yi = y0 + dy;
            bool vy = (yi >= 0) && (yi < D);
            int yc = min(max(yi, 0), D - 1);
            float fy = dy ? wy : 1.f - wy;
            #pragma unroll
            for (int dx = 0; dx < 2; dx++) {
                int xi = x0 + dx;
                bool vx = (xi >= 0) && (xi < D);
                int xc = min(max(xi, 0), D - 1);
                float fx = dx ? wx : 1.f - wx;
                offs[k] = (zc * D + yc) * D + xc;
                wts[k] = (vz && vy && vx) ? fz * fy * fx : 0.f;
                k++;
            }
        }
    }
    for (int c = 0; c < C; c++) {
        const float* sp = src + (size_t)c * vox;
        float acc = addend ? addend[(size_t)c * vox + idx] : 0.f;
        #pragma unroll
        for (int j = 0; j < 8; j++)
            acc += sp[offs[j]] * wts[j];
        out[(size_t)c * vox + idx] = acc;
    }
}

// concat input for disp_warp conv1: out[0:16] = yi+xi, out[16:32] = yi-xi
__global__ void make_cat(const float* __restrict__ xi, const float* __restrict__ yi,
                         float* __restrict__ out, int cvox /* 16*vox */) {
    int idx = blockIdx.x * blockDim.x + threadIdx.x;
    if (idx >= cvox) return;
    float a = xi[idx], b = yi[idx];
    out[idx] = b + a;
    out[cvox + idx] = b - a;
}

__global__ void scale_k(const float* __restrict__ in, float* __restrict__ out,
                        float s, int n) {
    int idx = blockIdx.x * blockDim.x + threadIdx.x;
    if (idx >= n) return;
    out[idx] = in[idx] * s;
}

// ---------------------------------------------------------------------------
// Host orchestration
// ---------------------------------------------------------------------------
struct Ptrs {
    float *bufA, *bufB, *xs, *ys, *warp16, *cat, *feat1, *feat2;
    float *flow, *vecA, *vecB, *up, *mu, *rsig;
};
static Ptrs P;
static bool g_inited = false;

static void init_ptrs() {
    cudaGetSymbolAddress((void**)&P.bufA, g_bufA);
    cudaGetSymbolAddress((void**)&P.bufB, g_bufB);
    cudaGetSymbolAddress((void**)&P.xs, g_xs);
    cudaGetSymbolAddress((void**)&P.ys, g_ys);
    cudaGetSymbolAddress((void**)&P.warp16, g_warp16);
    cudaGetSymbolAddress((void**)&P.cat, g_cat);
    cudaGetSymbolAddress((void**)&P.feat1, g_feat1);
    cudaGetSymbolAddress((void**)&P.feat2, g_feat2);
    cudaGetSymbolAddress((void**)&P.flow, g_flow);
    cudaGetSymbolAddress((void**)&P.vecA, g_vecA);
    cudaGetSymbolAddress((void**)&P.vecB, g_vecB);
    cudaGetSymbolAddress((void**)&P.up, g_up);
    cudaGetSymbolAddress((void**)&P.mu, g_mu);
    cudaGetSymbolAddress((void**)&P.rsig, g_rsig);
}

extern "C" void kernel_launch(void* const* d_in, const int* in_sizes, int n_in,
                              void* d_out, int out_size) {
    (void)in_sizes; (void)n_in; (void)out_size;
    if (!g_inited) { init_ptrs(); g_inited = true; }

    const float* x      = (const float*)d_in[0];
    const float* y      = (const float*)d_in[1];
    const float* enc_w1 = (const float*)d_in[2];
    const float* enc_b1 = (const float*)d_in[3];
    const float* enc_w2 = (const float*)d_in[4];
    const float* enc_b2 = (const float*)d_in[5];
    const float* enc_w3 = (const float*)d_in[6];
    const float* enc_b3 = (const float*)d_in[7];
    const float* prelu1 = (const float*)d_in[8];
    const float* prelu2 = (const float*)d_in[9];
    const float* prelu3 = (const float*)d_in[10];
    const float* dw_w1  = (const float*)d_in[11];
    const float* dw_b1  = (const float*)d_in[12];
    const float* dw_w2  = (const float*)d_in[13];
    const float* dw_b2  = (const float*)d_in[14];
    const float* dw_w3  = (const float*)d_in[15];
    const float* dw_b3  = (const float*)d_in[16];
    float* out = (float*)d_out;

    const int TB = 256;

    // ---------------- encoder (batch 2: [x;y]) ----------------
    cudaMemcpyAsync(P.bufA, x, (size_t)V64 * 4, cudaMemcpyDeviceToDevice);
    cudaMemcpyAsync(P.bufA + V64, y, (size_t)V64 * 4, cudaMemcpyDeviceToDevice);

    // conv1: 1 -> 16
    conv3x3x3<<<dim3((V64 + TB - 1) / TB, 16, 2), TB, 1 * 27 * 4>>>(
        P.bufA, enc_w1, enc_b1, P.bufB, 1, 64, 0);
    inorm_stats<<<32, 256>>>(P.bufB, P.mu, P.rsig, V64);
    norm_prelu<<<(2 * 16 * V64 + TB - 1) / TB, TB>>>(P.bufB, P.mu, P.rsig, prelu1,
                                                     V64, 2 * 16 * V64);
    // conv2: 16 -> 32
    conv3x3x3<<<dim3((V64 + TB - 1) / TB, 32, 2), TB, 16 * 27 * 4>>>(
        P.bufB, enc_w2, enc_b2, P.bufA, 16, 64, 0);
    inorm_stats<<<64, 256>>>(P.bufA, P.mu, P.rsig, V64);
    norm_prelu<<<(2 * 32 * V64 + TB - 1) / TB, TB>>>(P.bufA, P.mu, P.rsig, prelu2,
                                                     V64, 2 * 32 * V64);
    // conv3: 32 -> 16
    conv3x3x3<<<dim3((V64 + TB - 1) / TB, 16, 2), TB, 32 * 27 * 4>>>(
        P.bufA, enc_w3, enc_b3, P.bufB, 32, 64, 0);
    inorm_stats<<<32, 256>>>(P.bufB, P.mu, P.rsig, V64);
    norm_prelu<<<(2 * 16 * V64 + TB - 1) / TB, TB>>>(P.bufB, P.mu, P.rsig, prelu3,
                                                     V64, 2 * 16 * V64);

    // pyramid level 0 = encoder output
    cudaMemcpyAsync(P.xs, P.bufB, (size_t)16 * V64 * 4, cudaMemcpyDeviceToDevice);
    cudaMemcpyAsync(P.ys, P.bufB + (size_t)16 * V64, (size_t)16 * V64 * 4,
                    cudaMemcpyDeviceToDevice);

    // pyramid levels 1..4 (resize from previous level, matching reference)
    static const int OFF[5] = {0, 262144, 294912, 299008, 299520};
    for (int i = 1; i < 5; i++) {
        int inD = 64 >> (i - 1), outD = 64 >> i;
        int total = 16 * outD * outD * outD;
        resize_tri<<<(total + TB - 1) / TB, TB>>>(P.xs + (size_t)16 * OFF[i - 1],
                                                  P.xs + (size_t)16 * OFF[i],
                                                  16, inD, outD, 1.f);
        resize_tri<<<(total + TB - 1) / TB, TB>>>(P.ys + (size_t)16 * OFF[i - 1],
                                                  P.ys + (size_t)16 * OFF[i],
                                                  16, inD, outD, 1.f);
    }

    // output offsets (floats), level-0-first layout
    static const size_t int_off[5] = {0, 786432, 884736, 897024, 898560};
    const size_t pos_base = 898752;

    // ---------------- coarse-to-fine disp_warp loop ----------------
    for (int L = 4; L >= 0; L--) {
        int s = 64 >> L;
        int vox = s * s * s;
        int sb = (vox + TB - 1) / TB;
        const float* xi = P.xs + (size_t)16 * OFF[L];
        const float* yi = P.ys + (size_t)16 * OFF[L];

        const float* xi_use = xi;
        if (L < 4) {
            // xi = spatial_transform(xi, up_flow)
            warp_generic<<<sb, TB>>>(xi, P.up, nullptr, P.warp16, 16, s);
            xi_use = P.warp16;
        }

        // concat(yi+xi, yi-xi)
        make_cat<<<(16 * vox + TB - 1) / TB, TB>>>(xi_use, yi, P.cat, 16 * vox);

        // conv1 32->32 relu, conv2 32->27 relu, conv3 27->3
        conv3x3x3<<<dim3(sb, 32, 1), TB, 32 * 27 * 4>>>(
            P.cat, dw_w1 + (size_t)L * 32 * 32 * 27, dw_b1 + (size_t)L * 32,
            P.feat1, 32, s, 1);
        conv3x3x3<<<dim3(sb, 27, 1), TB, 32 * 27 * 4>>>(
            P.feat1, dw_w2 + (size_t)L * 27 * 32 * 27, dw_b2 + (size_t)L * 27,
            P.feat2, 32, s, 1);
        conv3x3x3<<<dim3(sb, 3, 1), TB, 27 * 27 * 4>>>(
            P.feat2, dw_w3 + (size_t)L * 3 * 27 * 27, dw_b3 + (size_t)L * 3,
            P.flow, 27, s, 0);

        // preint output
        cudaMemcpyAsync(out + int_off[L], P.flow, (size_t)3 * vox * 4,
                        cudaMemcpyDeviceToDevice);

        // vecint: scaling and squaring, 7 steps
        scale_k<<<(3 * vox + TB - 1) / TB, TB>>>(P.flow, P.vecA, 1.f / 128.f, 3 * vox);
        float* va = P.vecA;
        float* vb = P.vecB;
        for (int step = 0; step < 7; step++) {
            warp_generic<<<sb, TB>>>(va, va, va, vb, 3, s);
            float* tmp = va; va = vb; vb = tmp;
        }
        // result in va

        if (L < 4) {
            // flow = flow + spatial_transform(up_flow, flow)   (in-place safe)
            warp_generic<<<sb, TB>>>(P.up, va, va, va, 3, s);
        }

        // pos output
        cudaMemcpyAsync(out + pos_base + int_off[L], va, (size_t)3 * vox * 4,
                        cudaMemcpyDeviceToDevice);

        if (L > 0) {
            // up_flow = resize3(flow, 2s) * 2
            int outD = 2 * s;
            int total = 3 * outD * outD * outD;
            resize_tri<<<(total + TB - 1) / TB, TB>>>(va, P.up, 3, s, outD, 2.f);
        }
    }
}

// round 2
// speedup vs baseline: 2.7148x; 2.7148x over previous
#include <cuda_runtime.h>

// ---------------------------------------------------------------------------
// encoderOnlyComplex: VoxelMorph-style registration network, fp32.
// Round 1: register/smem-tiled 3D conv (the 96% of FLOPs), everything else
// kept from the correct baseline. Graph-capturable, allocation-free.
// ---------------------------------------------------------------------------

#define V64 262144            // 64^3
#define PYR_TOT 299584        // 64^3+32^3+16^3+8^3+4^3

// ---------------- static scratch (allocation-free rule) --------------------
__device__ float g_bufA[2 * 32 * V64];
__device__ float g_bufB[2 * 32 * V64];
__device__ float g_xs[16 * PYR_TOT];
__device__ float g_ys[16 * PYR_TOT];
__device__ float g_warp16[16 * V64];
__device__ float g_cat[32 * V64];
__device__ float g_feat1[32 * V64];
__device__ float g_feat2[27 * V64];
__device__ float g_flow[3 * V64];
__device__ float g_vecA[3 * V64];
__device__ float g_vecB[3 * V64];
__device__ float g_up[3 * V64];
__device__ float g_mu[64];
__device__ float g_rsig[64];
__device__ float g_wrep[32 * 27 * 32];   // repacked weights [ci][k][co_pad]

// ---------------------------------------------------------------------------
// Weight repack: w[co][ci][k] -> wr[ci][k][co_pad], padded co zero-filled.
// ---------------------------------------------------------------------------
__global__ void repack_w(const float* __restrict__ w, float* __restrict__ wr,
                         int Cin, int Cout, int COP) {
    int i = blockIdx.x * blockDim.x + threadIdx.x;
    int tot = Cin * 27 * COP;
    if (i >= tot) return;
    int co = i % COP;
    int k  = (i / COP) % 27;
    int ci = i / (COP * 27);
    wr[i] = (co < Cout) ? w[((size_t)co * Cin + ci) * 27 + k] : 0.f;
}

// ---------------------------------------------------------------------------
// Tiled direct 3x3x3 conv, pad 1, for D >= 16.
// Block = 128 threads: tx in [0,8) (x-quads), ty in [0,4) (y), tg in [0,4)
// (co group). Spatial tile 32 x 4 x 1; co coverage 4*JCO per block.
// Each thread: 4 consecutive x outputs for JCO output channels.
// Per ci: input halo tile (34x6x3, row stride 35 -> bank-conflict-free) and
// transposed weight slice in smem; inner loop is pure FMA on registers.
// ---------------------------------------------------------------------------
template <int JCO>
__global__ void conv_tiled(const float* __restrict__ in, const float* __restrict__ wr,
                           const float* __restrict__ bias, float* __restrict__ out,
                           int Cin, int Cout, int COP, int D, int relu,
                           int tilesX, int tilesY) {
    const int W = 4 * JCO;                    // co per block
    __shared__ __align__(16) float s_in[3 * 6 * 35];       // 630
    __shared__ __align__(16) float s_w[27 * 16];           // up to 432 used

    const int tid = threadIdx.x;
    const int tx = tid & 7;
    const int ty = (tid >> 3) & 3;
    const int tg = tid >> 5;

    int bx = blockIdx.x;
    const int tX = bx % tilesX;
    bx /= tilesX;
    const int tY = bx % tilesY;
    const int z  = bx / tilesY;
    const int n  = blockIdx.z;

    const int X0 = tX * 32;
    const int Y0 = tY * 4;
    const int coB = blockIdx.y * W;
    const int x0 = X0 + (tx << 2);
    const int yo = Y0 + ty;
    const int vox = D * D * D;

    float acc[JCO * 4];
    #pragma unroll
    for (int j = 0; j < JCO; j++) {
        int co = coB + tg * JCO + j;
        float b = (co < Cout) ? bias[co] : 0.f;
        #pragma unroll
        for (int xo = 0; xo < 4; xo++) acc[j * 4 + xo] = b;
    }

    const float* inN = in + (size_t)n * Cin * vox;

    for (int ci = 0; ci < Cin; ci++) {
        // weights: 27 * W floats, coalesced from repacked layout
        for (int i = tid; i < 27 * W; i += 128) {
            int k = i / W;
            int cl = i % W;
            s_w[k * W + cl] = wr[((size_t)ci * 27 + k) * COP + coB + cl];
        }
        // input halo tile: 3 z-planes x 6 rows x 34 cols
        const float* inC = inN + (size_t)ci * vox;
        for (int i = tid; i < 612; i += 128) {
            int kz = i / 204;
            int r  = (i % 204) / 34;
            int c  = i % 34;
            int zz = z - 1 + kz;
            int yy = Y0 - 1 + r;
            int xx = X0 - 1 + c;
            float v = 0.f;
            if ((unsigned)zz < (unsigned)D && (unsigned)yy < (unsigned)D &&
                (unsigned)xx < (unsigned)D)
                v = inC[((size_t)zz * D + yy) * D + xx];
            s_in[(kz * 6 + r) * 35 + c] = v;
        }
        __syncthreads();

        #pragma unroll
        for (int kz = 0; kz < 3; kz++) {
            #pragma unroll
            for (int ky = 0; ky < 3; ky++) {
                const float* bp = &s_in[(kz * 6 + ty + ky) * 35 + (tx << 2)];
                float v[6];
                #pragma unroll
                for (int i = 0; i < 6; i++) v[i] = bp[i];
                const float* wrow = &s_w[((kz * 3 + ky) * 3) * W + tg * JCO];
                float wk[3][JCO];
                #pragma unroll
                for (int kx = 0; kx < 3; kx++)
                    #pragma unroll
                    for (int j = 0; j < JCO; j++) wk[kx][j] = wrow[kx * W + j];
                #pragma unroll
                for (int kx = 0; kx < 3; kx++)
                    #pragma unroll
                    for (int j = 0; j < JCO; j++)
                        #pragma unroll
                        for (int xo = 0; xo < 4; xo++)
                            acc[j * 4 + xo] += v[kx + xo] * wk[kx][j];
            }
        }
        __syncthreads();
    }

    if (x0 < D) {
        #pragma unroll
        for (int j = 0; j < JCO; j++) {
            int co = coB + tg * JCO + j;
            if (co < Cout) {
                float* op = out + ((size_t)n * Cout + co) * vox +
                            ((size_t)z * D + yo) * D + x0;
                #pragma unroll
                for (int xo = 0; xo < 4; xo++) {
                    float r = acc[j * 4 + xo];
                    op[xo] = relu ? fmaxf(r, 0.f) : r;
                }
            }
        }
    }
}

// ---------------------------------------------------------------------------
// Fallback direct conv for tiny volumes (D < 16).
// ---------------------------------------------------------------------------
__global__ void conv3x3x3(const float* __restrict__ in, const float* __restrict__ w,
                          const float* __restrict__ bias, float* __restrict__ out,
                          int Cin, int D, int do_relu) {
    const int vox = D * D * D;
    const int co = blockIdx.y;
    const int n  = blockIdx.z;
    extern __shared__ float ws[];
    const int nw = Cin * 27;
    for (int i = threadIdx.x; i < nw; i += blockDim.x)
        ws[i] = w[(size_t)co * nw + i];
    __syncthreads();

    int idx = blockIdx.x * blockDim.x + threadIdx.x;
    if (idx >= vox) return;
    int x = idx % D;
    int t = idx / D;
    int y = t % D;
    int z = t / D;

    const float* inb = in + (size_t)n * Cin * vox;
    float acc = bias[co];
    for (int ci = 0; ci < Cin; ci++) {
        const float* ip = inb + (size_t)ci * vox;
        const float* wp = ws + ci * 27;
        #pragma unroll
        for (int kz = 0; kz < 3; kz++) {
            int zz = z + kz - 1;
            if ((unsigned)zz >= (unsigned)D) continue;
            #pragma unroll
            for (int ky = 0; ky < 3; ky++) {
                int yy = y + ky - 1;
                if ((unsigned)yy >= (unsigned)D) continue;
                const float* row = ip + ((size_t)zz * D + yy) * D;
                #pragma unroll
                for (int kx = 0; kx < 3; kx++) {
                    int xx = x + kx - 1;
                    if ((unsigned)xx >= (unsigned)D) continue;
                    acc += row[xx] * wp[kz * 9 + ky * 3 + kx];
                }
            }
        }
    }
    if (do_relu) acc = fmaxf(acc, 0.f);
    out[((size_t)n * gridDim.y + co) * vox + idx] = acc;
}

// ---------------------------------------------------------------------------
// Instance-norm statistics: one block per (n,c).
// ---------------------------------------------------------------------------
__global__ void inorm_stats(const float* __restrict__ in, float* __restrict__ mu,
                            float* __restrict__ rsig, int vox) {
    const int nc = blockIdx.x;
    const float* p = in + (size_t)nc * vox;
    float s = 0.f, s2 = 0.f;
    for (int i = threadIdx.x; i < vox; i += blockDim.x) {
        float v = p[i];
        s += v;
        s2 += v * v;
    }
    __shared__ float sh[256], sh2[256];
    sh[threadIdx.x] = s;
    sh2[threadIdx.x] = s2;
    __syncthreads();
    for (int o = 128; o > 0; o >>= 1) {
        if (threadIdx.x < o) {
            sh[threadIdx.x]  += sh[threadIdx.x + o];
            sh2[threadIdx.x] += sh2[threadIdx.x + o];
        }
        __syncthreads();
    }
    if (threadIdx.x == 0) {
        float m = sh[0] / (float)vox;
        float var = sh2[0] / (float)vox - m * m;
        mu[nc] = m;
        rsig[nc] = rsqrtf(var + 1e-5f);
    }
}

__global__ void norm_prelu(float* __restrict__ data, const float* __restrict__ mu,
                           const float* __restrict__ rsig, const float* __restrict__ alpha,
                           int vox, int total) {
    int idx = blockIdx.x * blockDim.x + threadIdx.x;
    if (idx >= total) return;
    int nc = idx / vox;
    float v = (data[idx] - mu[nc]) * rsig[nc];
    float a = *alpha;
    data[idx] = v >= 0.f ? v : a * v;
}

// ---------------------------------------------------------------------------
// Trilinear resize (matches reference per-axis composition on separable
// trilinear weights). gain applied.
// ---------------------------------------------------------------------------
__global__ void resize_tri(const float* __restrict__ in, float* __restrict__ out,
                           int C, int inD, int outD, float gain) {
    const int ov = outD * outD * outD;
    const int iv = inD * inD * inD;
    int idx = blockIdx.x * blockDim.x + threadIdx.x;
    int total = C * ov;
    if (idx >= total) return;
    int p = idx % ov;
    int c = idx / ov;
    int x = p % outD;
    int t = p / outD;
    int y = t % outD;
    int z = t / outD;

    float r = (float)(inD - 1) / (float)(outD - 1);
    float cz = z * r, cy = y * r, cx = x * r;
    int z0 = min(max((int)floorf(cz), 0), inD - 2);
    int y0 = min(max((int)floorf(cy), 0), inD - 2);
    int x0 = min(max((int)floorf(cx), 0), inD - 2);
    float tz = cz - (float)z0;
    float ty = cy - (float)y0;
    float tx = cx - (float)x0;

    const float* ip = in + (size_t)c * iv;
    size_t b000 = ((size_t)z0 * inD + y0) * inD + x0;
    size_t sy = inD, sz = (size_t)inD * inD;
    float v000 = ip[b000],           v001 = ip[b000 + 1];
    float v010 = ip[b000 + sy],      v011 = ip[b000 + sy + 1];
    float v100 = ip[b000 + sz],      v101 = ip[b000 + sz + 1];
    float v110 = ip[b000 + sz + sy], v111 = ip[b000 + sz + sy + 1];

    float c00 = v000 * (1.f - tx) + v001 * tx;
    float c01 = v010 * (1.f - tx) + v011 * tx;
    float c10 = v100 * (1.f - tx) + v101 * tx;
    float c11 = v110 * (1.f - tx) + v111 * tx;
    float c0 = c00 * (1.f - ty) + c01 * ty;
    float c1 = c10 * (1.f - ty) + c11 * ty;
    out[idx] = gain * (c0 * (1.f - tz) + c1 * tz);
}

// ---------------------------------------------------------------------------
// Generic warp (zero-padding grid-sample), optional addend.
// ---------------------------------------------------------------------------
__global__ void warp_generic(const float* __restrict__ src, const float* __restrict__ flow,
                             const float* __restrict__ addend, float* __restrict__ out,
                             int C, int D) {
    const int vox = D * D * D;
    int idx = blockIdx.x * blockDim.x + threadIdx.x;
    if (idx >= vox) return;
    int x = idx % D;
    int t = idx / D;
    int y = t % D;
    int z = t / D;

    float zz = (float)z + flow[idx];
    float yy = (float)y + flow[vox + idx];
    float xx = (float)x + flow[2 * vox + idx];

    float zf = floorf(zz), yf = floorf(yy), xf = floorf(xx);
    int z0 = (int)zf, y0 = (int)yf, x0 = (int)xf;
    float wz = zz - zf, wy = yy - yf, wx = xx - xf;

    int offs[8];
    float wts[8];
    int k = 0;
    #pragma unroll
    for (int dz = 0; dz < 2; dz++) {
        int zi = z0 + dz;
        bool vz = (zi >= 0) && (zi < D);
        int zc = min(max(zi, 0), D - 1);
        float fz = dz ? wz : 1.f - wz;
        #pragma unroll
        for (int dy = 0; dy < 2; dy++) {
            int yi = y0 + dy;
            bool vy = (yi >= 0) && (yi < D);
            int yc = min(max(yi, 0), D - 1);
            float fy = dy ? wy : 1.f - wy;
            #pragma unroll
            for (int dx = 0; dx < 2; dx++) {
                int xi = x0 + dx;
                bool vx = (xi >= 0) && (xi < D);
                int xc = min(max(xi, 0), D - 1);
                float fx = dx ? wx : 1.f - wx;
                offs[k] = (zc * D + yc) * D + xc;
                wts[k] = (vz && vy && vx) ? fz * fy * fx : 0.f;
                k++;
            }
        }
    }
    for (int c = 0; c < C; c++) {
        const float* sp = src + (size_t)c * vox;
        float acc = addend ? addend[(size_t)c * vox + idx] : 0.f;
        #pragma unroll
        for (int j = 0; j < 8; j++)
            acc += sp[offs[j]] * wts[j];
        out[(size_t)c * vox + idx] = acc;
    }
}

__global__ void make_cat(const float* __restrict__ xi, const float* __restrict__ yi,
                         float* __restrict__ out, int cvox) {
    int idx = blockIdx.x * blockDim.x + threadIdx.x;
    if (idx >= cvox) return;
    float a = xi[idx], b = yi[idx];
    out[idx] = b + a;
    out[cvox + idx] = b - a;
}

__global__ void scale_k(const float* __restrict__ in, float* __restrict__ out,
                        float s, int n) {
    int idx = blockIdx.x * blockDim.x + threadIdx.x;
    if (idx >= n) return;
    out[idx] = in[idx] * s;
}

// ---------------------------------------------------------------------------
// Host orchestration
// ---------------------------------------------------------------------------
struct Ptrs {
    float *bufA, *bufB, *xs, *ys, *warp16, *cat, *feat1, *feat2;
    float *flow, *vecA, *vecB, *up, *mu, *rsig, *wrep;
};
static Ptrs P;
static bool g_inited = false;

static void init_ptrs() {
    cudaGetSymbolAddress((void**)&P.bufA, g_bufA);
    cudaGetSymbolAddress((void**)&P.bufB, g_bufB);
    cudaGetSymbolAddress((void**)&P.xs, g_xs);
    cudaGetSymbolAddress((void**)&P.ys, g_ys);
    cudaGetSymbolAddress((void**)&P.warp16, g_warp16);
    cudaGetSymbolAddress((void**)&P.cat, g_cat);
    cudaGetSymbolAddress((void**)&P.feat1, g_feat1);
    cudaGetSymbolAddress((void**)&P.feat2, g_feat2);
    cudaGetSymbolAddress((void**)&P.flow, g_flow);
    cudaGetSymbolAddress((void**)&P.vecA, g_vecA);
    cudaGetSymbolAddress((void**)&P.vecB, g_vecB);
    cudaGetSymbolAddress((void**)&P.up, g_up);
    cudaGetSymbolAddress((void**)&P.mu, g_mu);
    cudaGetSymbolAddress((void**)&P.rsig, g_rsig);
    cudaGetSymbolAddress((void**)&P.wrep, g_wrep);
}

static void launch_conv(const float* in, const float* w, const float* b, float* outp,
                        int Cin, int Cout, int D, int relu, int N) {
    if (D >= 16) {
        int JCO = (Cout >= 8) ? 4 : 1;
        int W = 4 * JCO;
        int gy = (Cout + W - 1) / W;
        int COP = gy * W;
        int tot = Cin * 27 * COP;
        repack_w<<<(tot + 255) / 256, 256>>>(w, P.wrep, Cin, Cout, COP);
        int tilesX = (D + 31) / 32;
        int tilesY = D / 4;
        dim3 grid(tilesX * tilesY * D, gy, N);
        if (JCO == 4)
            conv_tiled<4><<<grid, 128>>>(in, P.wrep, b, outp, Cin, Cout, COP, D,
                                         relu, tilesX, tilesY);
        else
            conv_tiled<1><<<grid, 128>>>(in, P.wrep, b, outp, Cin, Cout, COP, D,
                                         relu, tilesX, tilesY);
    } else {
        int vox = D * D * D;
        dim3 grid((vox + 255) / 256, Cout, N);
        conv3x3x3<<<grid, 256, Cin * 27 * 4>>>(in, w, b, outp, Cin, D, relu);
    }
}

extern "C" void kernel_launch(void* const* d_in, const int* in_sizes, int n_in,
                              void* d_out, int out_size) {
    (void)in_sizes; (void)n_in; (void)out_size;
    if (!g_inited) { init_ptrs(); g_inited = true; }

    const float* x      = (const float*)d_in[0];
    const float* y      = (const float*)d_in[1];
    const float* enc_w1 = (const float*)d_in[2];
    const float* enc_b1 = (const float*)d_in[3];
    const float* enc_w2 = (const float*)d_in[4];
    const float* enc_b2 = (const float*)d_in[5];
    const float* enc_w3 = (const float*)d_in[6];
    const float* enc_b3 = (const float*)d_in[7];
    const float* prelu1 = (const float*)d_in[8];
    const float* prelu2 = (const float*)d_in[9];
    const float* prelu3 = (const float*)d_in[10];
    const float* dw_w1  = (const float*)d_in[11];
    const float* dw_b1  = (const float*)d_in[12];
    const float* dw_w2  = (const float*)d_in[13];
    const float* dw_b2  = (const float*)d_in[14];
    const float* dw_w3  = (const float*)d_in[15];
    const float* dw_b3  = (const float*)d_in[16];
    float* out = (float*)d_out;

    const int TB = 256;

    // ---------------- encoder (batch 2: [x;y]) ----------------
    cudaMemcpyAsync(P.bufA, x, (size_t)V64 * 4, cudaMemcpyDeviceToDevice);
    cudaMemcpyAsync(P.bufA + V64, y, (size_t)V64 * 4, cudaMemcpyDeviceToDevice);

    launch_conv(P.bufA, enc_w1, enc_b1, P.bufB, 1, 16, 64, 0, 2);
    inorm_stats<<<32, 256>>>(P.bufB, P.mu, P.rsig, V64);
    norm_prelu<<<(2 * 16 * V64 + TB - 1) / TB, TB>>>(P.bufB, P.mu, P.rsig, prelu1,
                                                     V64, 2 * 16 * V64);
    launch_conv(P.bufB, enc_w2, enc_b2, P.bufA, 16, 32, 64, 0, 2);
    inorm_stats<<<64, 256>>>(P.bufA, P.mu, P.rsig, V64);
    norm_prelu<<<(2 * 32 * V64 + TB - 1) / TB, TB>>>(P.bufA, P.mu, P.rsig, prelu2,
                                                     V64, 2 * 32 * V64);
    launch_conv(P.bufA, enc_w3, enc_b3, P.bufB, 32, 16, 64, 0, 2);
    inorm_stats<<<32, 256>>>(P.bufB, P.mu, P.rsig, V64);
    norm_prelu<<<(2 * 16 * V64 + TB - 1) / TB, TB>>>(P.bufB, P.mu, P.rsig, prelu3,
                                                     V64, 2 * 16 * V64);

    cudaMemcpyAsync(P.xs, P.bufB, (size_t)16 * V64 * 4, cudaMemcpyDeviceToDevice);
    cudaMemcpyAsync(P.ys, P.bufB + (size_t)16 * V64, (size_t)16 * V64 * 4,
                    cudaMemcpyDeviceToDevice);

    static const int OFF[5] = {0, 262144, 294912, 299008, 299520};
    for (int i = 1; i < 5; i++) {
        int inD = 64 >> (i - 1), outD = 64 >> i;
        int total = 16 * outD * outD * outD;
        resize_tri<<<(total + TB - 1) / TB, TB>>>(P.xs + (size_t)16 * OFF[i - 1],
                                                  P.xs + (size_t)16 * OFF[i],
                                                  16, inD, outD, 1.f);
        resize_tri<<<(total + TB - 1) / TB, TB>>>(P.ys + (size_t)16 * OFF[i - 1],
                                                  P.ys + (size_t)16 * OFF[i],
                                                  16, inD, outD, 1.f);
    }

    static const size_t int_off[5] = {0, 786432, 884736, 897024, 898560};
    const size_t pos_base = 898752;

    for (int L = 4; L >= 0; L--) {
        int s = 64 >> L;
        int vox = s * s * s;
        int sb = (vox + TB - 1) / TB;
        const float* xi = P.xs + (size_t)16 * OFF[L];
        const float* yi = P.ys + (size_t)16 * OFF[L];

        const float* xi_use = xi;
        if (L < 4) {
            warp_generic<<<sb, TB>>>(xi, P.up, nullptr, P.warp16, 16, s);
            xi_use = P.warp16;
        }

        make_cat<<<(16 * vox + TB - 1) / TB, TB>>>(xi_use, yi, P.cat, 16 * vox);

        launch_conv(P.cat,   dw_w1 + (size_t)L * 32 * 32 * 27, dw_b1 + (size_t)L * 32,
                    P.feat1, 32, 32, s, 1, 1);
        launch_conv(P.feat1, dw_w2 + (size_t)L * 27 * 32 * 27, dw_b2 + (size_t)L * 27,
                    P.feat2, 32, 27, s, 1, 1);
        launch_conv(P.feat2, dw_w3 + (size_t)L * 3 * 27 * 27,  dw_b3 + (size_t)L * 3,
                    P.flow,  27, 3,  s, 0, 1);

        cudaMemcpyAsync(out + int_off[L], P.flow, (size_t)3 * vox * 4,
                        cudaMemcpyDeviceToDevice);

        scale_k<<<(3 * vox + TB - 1) / TB, TB>>>(P.flow, P.vecA, 1.f / 128.f, 3 * vox);
        float* va = P.vecA;
        float* vb = P.vecB;
        for (int step = 0; step < 7; step++) {
            warp_generic<<<sb, TB>>>(va, va, va, vb, 3, s);
            float* tmp = va; va = vb; vb = tmp;
        }

        if (L < 4) {
            warp_generic<<<sb, TB>>>(P.up, va, va, va, 3, s);
        }

        cudaMemcpyAsync(out + pos_base + int_off[L], va, (size_t)3 * vox * 4,
                        cudaMemcpyDeviceToDevice);

        if (L > 0) {
            int outD = 2 * s;
            int total = 3 * outD * outD * outD;
            resize_tri<<<(total + TB - 1) / TB, TB>>>(va, P.up, 3, s, outD, 2.f);
        }
    }
}

// round 4
// speedup vs baseline: 3.6837x; 1.3569x over previous
#include <cuda_runtime.h>

// ---------------------------------------------------------------------------
// encoderOnlyComplex: VoxelMorph-style registration network, fp32.
// Round 3: resubmit of Round-2 source (infra failure, never measured).
// conv v2 (z-blocked, float4 smem), vectorized elementwise kernels.
// ---------------------------------------------------------------------------

#define V64 262144            // 64^3
#define PYR_TOT 299584        // 64^3+32^3+16^3+8^3+4^3

__device__ float g_bufA[2 * 32 * V64];
__device__ float g_bufB[2 * 32 * V64];
__device__ float g_xs[16 * PYR_TOT];
__device__ float g_ys[16 * PYR_TOT];
__device__ float g_warp16[16 * V64];
__device__ float g_cat[32 * V64];
__device__ float g_feat1[32 * V64];
__device__ float g_feat2[27 * V64];
__device__ float g_flow[3 * V64];
__device__ float g_vecA[3 * V64];
__device__ float g_vecB[3 * V64];
__device__ float g_up[3 * V64];
__device__ float g_mu[64];
__device__ float g_rsig[64];
__device__ float g_wrep[32 * 27 * 32];   // repacked weights [ci][k][co_pad]

// ---------------------------------------------------------------------------
__global__ void repack_w(const float* __restrict__ w, float* __restrict__ wr,
                         int Cin, int Cout, int COP) {
    int i = blockIdx.x * blockDim.x + threadIdx.x;
    int tot = Cin * 27 * COP;
    if (i >= tot) return;
    int co = i % COP;
    int k  = (i / COP) % 27;
    int ci = i / (COP * 27);
    wr[i] = (co < Cout) ? w[((size_t)co * Cin + ci) * 27 + k] : 0.f;
}

// ---------------------------------------------------------------------------
// Tiled 3x3x3 conv v2, pad 1, for D >= 16 (D multiple of 4).
// Block 128 thr: tx[0,8) x-quads, ty[0,4) rows, tg[0,4) co-groups.
// Tile: 32(x) x 4(y) x 2(z), co coverage 4*JCO. Each thread: 4 xo * JCO co
// * 2 zo = 8*JCO accumulators. Per ci: 4 z-planes (halo) staged in smem with
// 36-float row stride (LDS.128-friendly, conflict-free), weights as [k][W]
// for float4 broadcast loads. Inner loop pure FMA.
// ---------------------------------------------------------------------------
template <int JCO>
__global__ __launch_bounds__(128)
void conv_tiled2(const float* __restrict__ in, const float* __restrict__ wr,
                 const float* __restrict__ bias, float* __restrict__ out,
                 int Cin, int Cout, int COP, int D, int relu,
                 int tilesX, int tilesY) {
    const int W = 4 * JCO;
    __shared__ __align__(16) float s_in[4 * 6 * 36];   // 864
    __shared__ __align__(16) float s_w[27 * 16];

    const int tid = threadIdx.x;
    const int tx = tid & 7;
    const int ty = (tid >> 3) & 3;
    const int tg = tid >> 5;

    int bx = blockIdx.x;
    const int tX = bx % tilesX;
    bx /= tilesX;
    const int tY = bx % tilesY;
    const int tZ = bx / tilesY;
    const int n  = blockIdx.z;

    const int X0 = tX * 32;
    const int Y0 = tY * 4;
    const int Z0 = tZ * 2;
    const int coB = blockIdx.y * W;
    const int x0 = X0 + (tx << 2);
    const int yo = Y0 + ty;
    const int vox = D * D * D;

    float acc[2 * JCO * 4];
    #pragma unroll
    for (int j = 0; j < JCO; j++) {
        int co = coB + tg * JCO + j;
        float b = (co < Cout) ? bias[co] : 0.f;
        #pragma unroll
        for (int zo = 0; zo < 2; zo++)
            #pragma unroll
            for (int xo = 0; xo < 4; xo++) acc[(zo * JCO + j) * 4 + xo] = b;
    }

    const float* inN = in + (size_t)n * Cin * vox;

    for (int ci = 0; ci < Cin; ci++) {
        // weights: 27*W floats
        for (int i = tid; i < 27 * W; i += 128)
            s_w[(i / W) * W + (i % W)] =
                wr[((size_t)ci * 27 + i / W) * COP + coB + (i % W)];
        // input: 4 z-planes x 6 rows x 34 cols (halo), stride-36 rows
        const float* inC = inN + (size_t)ci * vox;
        for (int i = tid; i < 816; i += 128) {
            int p = i / 204;
            int r = (i % 204) / 34;
            int c = i % 34;
            int zz = Z0 - 1 + p;
            int yy = Y0 - 1 + r;
            int xx = X0 - 1 + c;
            float v = 0.f;
            if ((unsigned)zz < (unsigned)D && (unsigned)yy < (unsigned)D &&
                (unsigned)xx < (unsigned)D)
                v = __ldg(&inC[((size_t)zz * D + yy) * D + xx]);
            s_in[(p * 6 + r) * 36 + c] = v;
        }
        __syncthreads();

        #pragma unroll
        for (int kz = 0; kz < 3; kz++) {
            #pragma unroll
            for (int ky = 0; ky < 3; ky++) {
                const int k0 = kz * 9 + ky * 3;
                float wk[3][JCO];
                if (JCO == 4) {
                    #pragma unroll
                    for (int kx = 0; kx < 3; kx++) {
                        float4 w4 = *(const float4*)&s_w[(k0 + kx) * 16 + tg * 4];
                        wk[kx][0] = w4.x; wk[kx][1] = w4.y;
                        wk[kx][2] = w4.z; wk[kx][3] = w4.w;
                    }
                } else {
                    #pragma unroll
                    for (int kx = 0; kx < 3; kx++)
                        wk[kx][0] = s_w[(k0 + kx) * W + tg];
                }
                #pragma unroll
                for (int zo = 0; zo < 2; zo++) {
                    const float* bp =
                        &s_in[((kz + zo) * 6 + ty + ky) * 36 + (tx << 2)];
                    float4 a = *(const float4*)bp;
                    float4 b = *(const float4*)(bp + 4);
                    float v[6] = {a.x, a.y, a.z, a.w, b.x, b.y};
                    #pragma unroll
                    for (int kx = 0; kx < 3; kx++)
                        #pragma unroll
                        for (int j = 0; j < JCO; j++)
                            #pragma unroll
                            for (int xo = 0; xo < 4; xo++)
                                acc[(zo * JCO + j) * 4 + xo] +=
                                    v[kx + xo] * wk[kx][j];
                }
            }
        }
        __syncthreads();
    }

    if (x0 < D) {
        #pragma unroll
        for (int zo = 0; zo < 2; zo++) {
            int z = Z0 + zo;
            #pragma unroll
            for (int j = 0; j < JCO; j++) {
                int co = coB + tg * JCO + j;
                if (co < Cout) {
                    float4 r;
                    float* a = &acc[(zo * JCO + j) * 4];
                    r.x = a[0]; r.y = a[1]; r.z = a[2]; r.w = a[3];
                    if (relu) {
                        r.x = fmaxf(r.x, 0.f); r.y = fmaxf(r.y, 0.f);
                        r.z = fmaxf(r.z, 0.f); r.w = fmaxf(r.w, 0.f);
                    }
                    *(float4*)(out + ((size_t)n * Cout + co) * vox +
                               ((size_t)z * D + yo) * D + x0) = r;
                }
            }
        }
    }
}

// ---------------------------------------------------------------------------
// Fallback direct conv for tiny volumes (D < 16).
// ---------------------------------------------------------------------------
__global__ void conv3x3x3(const float* __restrict__ in, const float* __restrict__ w,
                          const float* __restrict__ bias, float* __restrict__ out,
                          int Cin, int D, int do_relu) {
    const int vox = D * D * D;
    const int co = blockIdx.y;
    const int n  = blockIdx.z;
    extern __shared__ float ws[];
    const int nw = Cin * 27;
    for (int i = threadIdx.x; i < nw; i += blockDim.x)
        ws[i] = w[(size_t)co * nw + i];
    __syncthreads();

    int idx = blockIdx.x * blockDim.x + threadIdx.x;
    if (idx >= vox) return;
    int x = idx % D;
    int t = idx / D;
    int y = t % D;
    int z = t / D;

    const float* inb = in + (size_t)n * Cin * vox;
    float acc = bias[co];
    for (int ci = 0; ci < Cin; ci++) {
        const float* ip = inb + (size_t)ci * vox;
        const float* wp = ws + ci * 27;
        #pragma unroll
        for (int kz = 0; kz < 3; kz++) {
            int zz = z + kz - 1;
            if ((unsigned)zz >= (unsigned)D) continue;
            #pragma unroll
            for (int ky = 0; ky < 3; ky++) {
                int yy = y + ky - 1;
                if ((unsigned)yy >= (unsigned)D) continue;
                const float* row = ip + ((size_t)zz * D + yy) * D;
                #pragma unroll
                for (int kx = 0; kx < 3; kx++) {
                    int xx = x + kx - 1;
                    if ((unsigned)xx >= (unsigned)D) continue;
                    acc += row[xx] * wp[kz * 9 + ky * 3 + kx];
                }
            }
        }
    }
    if (do_relu) acc = fmaxf(acc, 0.f);
    out[((size_t)n * gridDim.y + co) * vox + idx] = acc;
}

// ---------------------------------------------------------------------------
__global__ void inorm_stats(const float* __restrict__ in, float* __restrict__ mu,
                            float* __restrict__ rsig, int vox) {
    const int nc = blockIdx.x;
    const float4* p = (const float4*)(in + (size_t)nc * vox);
    int n4 = vox >> 2;
    float s = 0.f, s2 = 0.f;
    for (int i = threadIdx.x; i < n4; i += 256) {
        float4 v = p[i];
        s  += v.x + v.y + v.z + v.w;
        s2 += v.x * v.x + v.y * v.y + v.z * v.z + v.w * v.w;
    }
    __shared__ float sh[256], sh2[256];
    sh[threadIdx.x] = s;
    sh2[threadIdx.x] = s2;
    __syncthreads();
    for (int o = 128; o > 0; o >>= 1) {
        if (threadIdx.x < o) {
            sh[threadIdx.x]  += sh[threadIdx.x + o];
            sh2[threadIdx.x] += sh2[threadIdx.x + o];
        }
        __syncthreads();
    }
    if (threadIdx.x == 0) {
        float m = sh[0] / (float)vox;
        float var = sh2[0] / (float)vox - m * m;
        mu[nc] = m;
        rsig[nc] = rsqrtf(var + 1e-5f);
    }
}

// Normalize + PReLU, in place. grid = (vox/1024, NC), block 256, float4.
__global__ void norm_prelu(float* __restrict__ data, const float* __restrict__ mu,
                           const float* __restrict__ rsig, const float* __restrict__ alpha,
                           int vox) {
    int nc = blockIdx.y;
    int i = (blockIdx.x * 256 + threadIdx.x) << 2;
    if (i >= vox) return;
    float m = mu[nc], rs = rsig[nc], a = *alpha;
    float4* p = (float4*)(data + (size_t)nc * vox + i);
    float4 v = *p;
    v.x = (v.x - m) * rs; v.x = v.x >= 0.f ? v.x : a * v.x;
    v.y = (v.y - m) * rs; v.y = v.y >= 0.f ? v.y : a * v.y;
    v.z = (v.z - m) * rs; v.z = v.z >= 0.f ? v.z : a * v.z;
    v.w = (v.w - m) * rs; v.w = v.w >= 0.f ? v.w : a * v.w;
    *p = v;
}

// ---------------------------------------------------------------------------
__global__ void resize_tri(const float* __restrict__ in, float* __restrict__ out,
                           int C, int inD, int outD, float gain) {
    const int ov = outD * outD * outD;
    const int iv = inD * inD * inD;
    int idx = blockIdx.x * blockDim.x + threadIdx.x;
    int total = C * ov;
    if (idx >= total) return;
    int p = idx % ov;
    int c = idx / ov;
    int x = p % outD;
    int t = p / outD;
    int y = t % outD;
    int z = t / outD;

    float r = (float)(inD - 1) / (float)(outD - 1);
    float cz = z * r, cy = y * r, cx = x * r;
    int z0 = min(max((int)floorf(cz), 0), inD - 2);
    int y0 = min(max((int)floorf(cy), 0), inD - 2);
    int x0 = min(max((int)floorf(cx), 0), inD - 2);
    float tz = cz - (float)z0;
    float ty = cy - (float)y0;
    float tx = cx - (float)x0;

    const float* ip = in + (size_t)c * iv;
    size_t b000 = ((size_t)z0 * inD + y0) * inD + x0;
    size_t sy = inD, sz = (size_t)inD * inD;
    float v000 = ip[b000],           v001 = ip[b000 + 1];
    float v010 = ip[b000 + sy],      v011 = ip[b000 + sy + 1];
    float v100 = ip[b000 + sz],      v101 = ip[b000 + sz + 1];
    float v110 = ip[b000 + sz + sy], v111 = ip[b000 + sz + sy + 1];

    float c00 = v000 * (1.f - tx) + v001 * tx;
    float c01 = v010 * (1.f - tx) + v011 * tx;
    float c10 = v100 * (1.f - tx) + v101 * tx;
    float c11 = v110 * (1.f - tx) + v111 * tx;
    float c0 = c00 * (1.f - ty) + c01 * ty;
    float c1 = c10 * (1.f - ty) + c11 * ty;
    out[idx] = gain * (c0 * (1.f - tz) + c1 * tz);
}

// ---------------------------------------------------------------------------
__global__ void warp_generic(const float* __restrict__ src, const float* __restrict__ flow,
                             const float* __restrict__ addend, float* __restrict__ out,
                             int C, int D) {
    const int vox = D * D * D;
    int idx = blockIdx.x * blockDim.x + threadIdx.x;
    if (idx >= vox) return;
    int x = idx % D;
    int t = idx / D;
    int y = t % D;
    int z = t / D;

    float zz = (float)z + flow[idx];
    float yy = (float)y + flow[vox + idx];
    float xx = (float)x + flow[2 * vox + idx];

    float zf = floorf(zz), yf = floorf(yy), xf = floorf(xx);
    int z0 = (int)zf, y0 = (int)yf, x0 = (int)xf;
    float wz = zz - zf, wy = yy - yf, wx = xx - xf;

    int offs[8];
    float wts[8];
    int k = 0;
    #pragma unroll
    for (int dz = 0; dz < 2; dz++) {
        int zi = z0 + dz;
        bool vz = (zi >= 0) && (zi < D);
        int zc = min(max(zi, 0), D - 1);
        float fz = dz ? wz : 1.f - wz;
        #pragma unroll
        for (int dy = 0; dy < 2; dy++) {
            int yi = y0 + dy;
            bool vy = (yi >= 0) && (yi < D);
            int yc = min(max(yi, 0), D - 1);
            float fy = dy ? wy : 1.f - wy;
            #pragma unroll
            for (int dx = 0; dx < 2; dx++) {
                int xi = x0 + dx;
                bool vx = (xi >= 0) && (xi < D);
                int xc = min(max(xi, 0), D - 1);
                float fx = dx ? wx : 1.f - wx;
                offs[k] = (zc * D + yc) * D + xc;
                wts[k] = (vz && vy && vx) ? fz * fy * fx : 0.f;
                k++;
            }
        }
    }
    for (int c = 0; c < C; c++) {
        const float* sp = src + (size_t)c * vox;
        float acc = addend ? addend[(size_t)c * vox + idx] : 0.f;
        #pragma unroll
        for (int j = 0; j < 8; j++)
            acc += sp[offs[j]] * wts[j];
        out[(size_t)c * vox + idx] = acc;
    }
}

__global__ void make_cat(const float* __restrict__ xi, const float* __restrict__ yi,
                         float* __restrict__ out, int cvox) {
    int i = (blockIdx.x * blockDim.x + threadIdx.x) << 2;
    if (i >= cvox) return;
    float4 a = *(const float4*)(xi + i);
    float4 b = *(const float4*)(yi + i);
    float4 s, d;
    s.x = b.x + a.x; s.y = b.y + a.y; s.z = b.z + a.z; s.w = b.w + a.w;
    d.x = b.x - a.x; d.y = b.y - a.y; d.z = b.z - a.z; d.w = b.w - a.w;
    *(float4*)(out + i) = s;
    *(float4*)(out + cvox + i) = d;
}

__global__ void scale_k(const float* __restrict__ in, float* __restrict__ out,
                        float s, int n) {
    int i = (blockIdx.x * blockDim.x + threadIdx.x) << 2;
    if (i >= n) return;
    float4 v = *(const float4*)(in + i);
    v.x *= s; v.y *= s; v.z *= s; v.w *= s;
    *(float4*)(out + i) = v;
}

// ---------------------------------------------------------------------------
struct Ptrs {
    float *bufA, *bufB, *xs, *ys, *warp16, *cat, *feat1, *feat2;
    float *flow, *vecA, *vecB, *up, *mu, *rsig, *wrep;
};
static Ptrs P;
static bool g_inited = false;

static void init_ptrs() {
    cudaGetSymbolAddress((void**)&P.bufA, g_bufA);
    cudaGetSymbolAddress((void**)&P.bufB, g_bufB);
    cudaGetSymbolAddress((void**)&P.xs, g_xs);
    cudaGetSymbolAddress((void**)&P.ys, g_ys);
    cudaGetSymbolAddress((void**)&P.warp16, g_warp16);
    cudaGetSymbolAddress((void**)&P.cat, g_cat);
    cudaGetSymbolAddress((void**)&P.feat1, g_feat1);
    cudaGetSymbolAddress((void**)&P.feat2, g_feat2);
    cudaGetSymbolAddress((void**)&P.flow, g_flow);
    cudaGetSymbolAddress((void**)&P.vecA, g_vecA);
    cudaGetSymbolAddress((void**)&P.vecB, g_vecB);
    cudaGetSymbolAddress((void**)&P.up, g_up);
    cudaGetSymbolAddress((void**)&P.mu, g_mu);
    cudaGetSymbolAddress((void**)&P.rsig, g_rsig);
    cudaGetSymbolAddress((void**)&P.wrep, g_wrep);
}

static void launch_conv(const float* in, const float* w, const float* b, float* outp,
                        int Cin, int Cout, int D, int relu, int N) {
    if (D >= 16) {
        int JCO = (Cout >= 8) ? 4 : 1;
        int W = 4 * JCO;
        int gy = (Cout + W - 1) / W;
        int COP = gy * W;
        int tot = Cin * 27 * COP;
        repack_w<<<(tot + 255) / 256, 256>>>(w, P.wrep, Cin, Cout, COP);
        int tilesX = (D + 31) / 32;
        int tilesY = D / 4;
        int tilesZ = D / 2;
        dim3 grid(tilesX * tilesY * tilesZ, gy, N);
        if (JCO == 4)
            conv_tiled2<4><<<grid, 128>>>(in, P.wrep, b, outp, Cin, Cout, COP, D,
                                          relu, tilesX, tilesY);
        else
            conv_tiled2<1><<<grid, 128>>>(in, P.wrep, b, outp, Cin, Cout, COP, D,
                                          relu, tilesX, tilesY);
    } else {
        int vox = D * D * D;
        dim3 grid((vox + 255) / 256, Cout, N);
        conv3x3x3<<<grid, 256, Cin * 27 * 4>>>(in, w, b, outp, Cin, D, relu);
    }
}

extern "C" void kernel_launch(void* const* d_in, const int* in_sizes, int n_in,
                              void* d_out, int out_size) {
    (void)in_sizes; (void)n_in; (void)out_size;
    if (!g_inited) { init_ptrs(); g_inited = true; }

    const float* x      = (const float*)d_in[0];
    const float* y      = (const float*)d_in[1];
    const float* enc_w1 = (const float*)d_in[2];
    const float* enc_b1 = (const float*)d_in[3];
    const float* enc_w2 = (const float*)d_in[4];
    const float* enc_b2 = (const float*)d_in[5];
    const float* enc_w3 = (const float*)d_in[6];
    const float* enc_b3 = (const float*)d_in[7];
    const float* prelu1 = (const float*)d_in[8];
    const float* prelu2 = (const float*)d_in[9];
    const float* prelu3 = (const float*)d_in[10];
    const float* dw_w1  = (const float*)d_in[11];
    const float* dw_b1  = (const float*)d_in[12];
    const float* dw_w2  = (const float*)d_in[13];
    const float* dw_b2  = (const float*)d_in[14];
    const float* dw_w3  = (const float*)d_in[15];
    const float* dw_b3  = (const float*)d_in[16];
    float* out = (float*)d_out;

    const int TB = 256;

    cudaMemcpyAsync(P.bufA, x, (size_t)V64 * 4, cudaMemcpyDeviceToDevice);
    cudaMemcpyAsync(P.bufA + V64, y, (size_t)V64 * 4, cudaMemcpyDeviceToDevice);

    launch_conv(P.bufA, enc_w1, enc_b1, P.bufB, 1, 16, 64, 0, 2);
    inorm_stats<<<32, 256>>>(P.bufB, P.mu, P.rsig, V64);
    norm_prelu<<<dim3(V64 / 1024, 32), 256>>>(P.bufB, P.mu, P.rsig, prelu1, V64);
    launch_conv(P.bufB, enc_w2, enc_b2, P.bufA, 16, 32, 64, 0, 2);
    inorm_stats<<<64, 256>>>(P.bufA, P.mu, P.rsig, V64);
    norm_prelu<<<dim3(V64 / 1024, 64), 256>>>(P.bufA, P.mu, P.rsig, prelu2, V64);
    launch_conv(P.bufA, enc_w3, enc_b3, P.bufB, 32, 16, 64, 0, 2);
    inorm_stats<<<32, 256>>>(P.bufB, P.mu, P.rsig, V64);
    norm_prelu<<<dim3(V64 / 1024, 32), 256>>>(P.bufB, P.mu, P.rsig, prelu3, V64);

    cudaMemcpyAsync(P.xs, P.bufB, (size_t)16 * V64 * 4, cudaMemcpyDeviceToDevice);
    cudaMemcpyAsync(P.ys, P.bufB + (size_t)16 * V64, (size_t)16 * V64 * 4,
                    cudaMemcpyDeviceToDevice);

    static const int OFF[5] = {0, 262144, 294912, 299008, 299520};
    for (int i = 1; i < 5; i++) {
        int inD = 64 >> (i - 1), outD = 64 >> i;
        int total = 16 * outD * outD * outD;
        resize_tri<<<(total + TB - 1) / TB, TB>>>(P.xs + (size_t)16 * OFF[i - 1],
                                                  P.xs + (size_t)16 * OFF[i],
                                                  16, inD, outD, 1.f);
        resize_tri<<<(total + TB - 1) / TB, TB>>>(P.ys + (size_t)16 * OFF[i - 1],
                                                  P.ys + (size_t)16 * OFF[i],
                                                  16, inD, outD, 1.f);
    }

    static const size_t int_off[5] = {0, 786432, 884736, 897024, 898560};
    const size_t pos_base = 898752;

    for (int L = 4; L >= 0; L--) {
        int s = 64 >> L;
        int vox = s * s * s;
        int sb = (vox + TB - 1) / TB;
        const float* xi = P.xs + (size_t)16 * OFF[L];
        const float* yi = P.ys + (size_t)16 * OFF[L];

        const float* xi_use = xi;
        if (L < 4) {
            warp_generic<<<sb, TB>>>(xi, P.up, nullptr, P.warp16, 16, s);
            xi_use = P.warp16;
        }

        make_cat<<<(16 * vox / 4 + TB - 1) / TB, TB>>>(xi_use, yi, P.cat, 16 * vox);

        launch_conv(P.cat,   dw_w1 + (size_t)L * 32 * 32 * 27, dw_b1 + (size_t)L * 32,
                    P.feat1, 32, 32, s, 1, 1);
        launch_conv(P.feat1, dw_w2 + (size_t)L * 27 * 32 * 27, dw_b2 + (size_t)L * 27,
                    P.feat2, 32, 27, s, 1, 1);
        launch_conv(P.feat2, dw_w3 + (size_t)L * 3 * 27 * 27,  dw_b3 + (size_t)L * 3,
                    P.flow,  27, 3,  s, 0, 1);

        cudaMemcpyAsync(out + int_off[L], P.flow, (size_t)3 * vox * 4,
                        cudaMemcpyDeviceToDevice);

        scale_k<<<(3 * vox / 4 + TB - 1) / TB, TB>>>(P.flow, P.vecA, 1.f / 128.f,
                                                     3 * vox);
        float* va = P.vecA;
        float* vb = P.vecB;
        for (int step = 0; step < 7; step++) {
            warp_generic<<<sb, TB>>>(va, va, va, vb, 3, s);
            float* tmp = va; va = vb; vb = tmp;
        }

        if (L < 4) {
            warp_generic<<<sb, TB>>>(P.up, va, va, va, 3, s);
        }

        cudaMemcpyAsync(out + pos_base + int_off[L], va, (size_t)3 * vox * 4,
                        cudaMemcpyDeviceToDevice);

        if (L > 0) {
            int outD = 2 * s;
            int total = 3 * outD * outD * outD;
            resize_tri<<<(total + TB - 1) / TB, TB>>>(va, P.up, 3, s, outD, 2.f);
        }
    }
}

// round 5
// speedup vs baseline: 3.7982x; 1.0311x over previous
#include <cuda_runtime.h>

// ---------------------------------------------------------------------------
// encoderOnlyComplex: VoxelMorph-style registration network, fp32.
// Round 4: conv ZO=4 z-blocking, single repack kernel, fused warp+cat,
// fused single-block vecint for small levels, level-0 pyramid aliasing.
// ---------------------------------------------------------------------------

#define V64 262144            // 64^3
#define PYR_TOT 299584

__device__ float g_bufA[2 * 32 * V64];
__device__ float g_bufB[2 * 32 * V64];
__device__ float g_xs[16 * PYR_TOT];
__device__ float g_ys[16 * PYR_TOT];
__device__ float g_cat[32 * V64];
__device__ float g_feat1[32 * V64];
__device__ float g_feat2[27 * V64];
__device__ float g_flow[3 * V64];
__device__ float g_vecA[3 * V64];
__device__ float g_vecB[3 * V64];
__device__ float g_up[3 * V64];
__device__ float g_mu[64];
__device__ float g_rsig[64];
__device__ float g_wrepAll[202716];

// Repack table (12 tiled convs): enc1,enc2,enc3, then dw1/dw2/dw3 for L=0,1,2
// id:            0    1     2     3     4     5     6      7      8      9      10     11
// Cin:           1    16    32    32    32    27    32     32     27     32     32     27
// Cout:          16   32    16    32    27    3     32     27     3      32     27     3
// COP:           16   32    16    32    32    4     32     32     4      32     32     4
// off:           0    432   14256 28080 55728 83376 86292  113940 141588 144504 172152 199800

__global__ void repack_all(const float* __restrict__ e1, const float* __restrict__ e2,
                           const float* __restrict__ e3, const float* __restrict__ w1,
                           const float* __restrict__ w2, const float* __restrict__ w3,
                           float* __restrict__ wr) {
    const int CIN[12]  = {1,16,32, 32,32,27, 32,32,27, 32,32,27};
    const int COUT[12] = {16,32,16, 32,27,3, 32,27,3, 32,27,3};
    const int COP[12]  = {16,32,16, 32,32,4, 32,32,4, 32,32,4};
    const int OFF[12]  = {0,432,14256, 28080,55728,83376,
                          86292,113940,141588, 144504,172152,199800};
    int id = blockIdx.y;
    int cin = CIN[id], cout = COUT[id], cop = COP[id];
    int tot = cin * 27 * cop;
    int i = blockIdx.x * blockDim.x + threadIdx.x;
    if (i >= tot) return;
    const float* src;
    if (id == 0) src = e1;
    else if (id == 1) src = e2;
    else if (id == 2) src = e3;
    else {
        int l = (id - 3) / 3, j = (id - 3) % 3;
        const float* base = (j == 0) ? w1 : (j == 1) ? w2 : w3;
        src = base + (size_t)l * cout * cin * 27;
    }
    int co = i % cop;
    int k  = (i / cop) % 27;
    int ci = i / (cop * 27);
    wr[OFF[id] + i] = (co < cout) ? src[((size_t)co * cin + ci) * 27 + k] : 0.f;
}

// ---------------------------------------------------------------------------
// Tiled 3x3x3 conv v3: tile 32(x) x 4(y) x 4(z), co coverage 4*JCO.
// Block 128 thr: tx[0,8) x-quads, ty[0,4), tg[0,4) co-groups.
// Per thread: 4 xo * JCO co * 4 zo accumulators. Per ci: 6 halo z-planes in
// smem (row stride 36, LDS.128-friendly), weights [k][W] broadcast float4.
// ---------------------------------------------------------------------------
template <int JCO>
__global__ __launch_bounds__(128)
void conv_tiled3(const float* __restrict__ in, const float* __restrict__ wr,
                 const float* __restrict__ bias, float* __restrict__ out,
                 int Cin, int Cout, int COP, int D, int relu,
                 int tilesX, int tilesY) {
    const int W = 4 * JCO;
    __shared__ __align__(16) float s_in[6 * 6 * 36];   // 1296
    __shared__ __align__(16) float s_w[27 * 16];

    const int tid = threadIdx.x;
    const int tx = tid & 7;
    const int ty = (tid >> 3) & 3;
    const int tg = tid >> 5;

    int bx = blockIdx.x;
    const int tX = bx % tilesX;
    bx /= tilesX;
    const int tY = bx % tilesY;
    const int tZ = bx / tilesY;
    const int n  = blockIdx.z;

    const int X0 = tX * 32;
    const int Y0 = tY * 4;
    const int Z0 = tZ * 4;
    const int coB = blockIdx.y * W;
    const int x0 = X0 + (tx << 2);
    const int yo = Y0 + ty;
    const int vox = D * D * D;

    float acc[4 * JCO * 4];
    #pragma unroll
    for (int j = 0; j < JCO; j++) {
        int co = coB + tg * JCO + j;
        float b = (co < Cout) ? bias[co] : 0.f;
        #pragma unroll
        for (int zo = 0; zo < 4; zo++)
            #pragma unroll
            for (int xo = 0; xo < 4; xo++) acc[(zo * JCO + j) * 4 + xo] = b;
    }

    const float* inN = in + (size_t)n * Cin * vox;

    for (int ci = 0; ci < Cin; ci++) {
        for (int i = tid; i < 27 * W; i += 128)
            s_w[(i / W) * W + (i % W)] =
                wr[((size_t)ci * 27 + i / W) * COP + coB + (i % W)];
        const float* inC = inN + (size_t)ci * vox;
        for (int i = tid; i < 1224; i += 128) {
            int p = i / 204;
            int r = (i % 204) / 34;
            int c = i % 34;
            int zz = Z0 - 1 + p;
            int yy = Y0 - 1 + r;
            int xx = X0 - 1 + c;
            float v = 0.f;
            if ((unsigned)zz < (unsigned)D && (unsigned)yy < (unsigned)D &&
                (unsigned)xx < (unsigned)D)
                v = __ldg(&inC[((size_t)zz * D + yy) * D + xx]);
            s_in[(p * 6 + r) * 36 + c] = v;
        }
        __syncthreads();

        #pragma unroll
        for (int kz = 0; kz < 3; kz++) {
            #pragma unroll
            for (int ky = 0; ky < 3; ky++) {
                const int k0 = kz * 9 + ky * 3;
                float wk[3][JCO];
                if (JCO == 4) {
                    #pragma unroll
                    for (int kx = 0; kx < 3; kx++) {
                        float4 w4 = *(const float4*)&s_w[(k0 + kx) * 16 + tg * 4];
                        wk[kx][0] = w4.x; wk[kx][1] = w4.y;
                        wk[kx][2] = w4.z; wk[kx][3] = w4.w;
                    }
                } else {
                    #pragma unroll
                    for (int kx = 0; kx < 3; kx++)
                        wk[kx][0] = s_w[(k0 + kx) * W + tg];
                }
                #pragma unroll
                for (int zo = 0; zo < 4; zo++) {
                    const float* bp =
                        &s_in[((kz + zo) * 6 + ty + ky) * 36 + (tx << 2)];
                    float4 a = *(const float4*)bp;
                    float4 b = *(const float4*)(bp + 4);
                    float v[6] = {a.x, a.y, a.z, a.w, b.x, b.y};
                    #pragma unroll
                    for (int kx = 0; kx < 3; kx++)
                        #pragma unroll
                        for (int j = 0; j < JCO; j++)
                            #pragma unroll
                            for (int xo = 0; xo < 4; xo++)
                                acc[(zo * JCO + j) * 4 + xo] +=
                                    v[kx + xo] * wk[kx][j];
                }
            }
        }
        __syncthreads();
    }

    if (x0 < D) {
        #pragma unroll
        for (int zo = 0; zo < 4; zo++) {
            int z = Z0 + zo;
            #pragma unroll
            for (int j = 0; j < JCO; j++) {
                int co = coB + tg * JCO + j;
                if (co < Cout) {
                    float4 r;
                    float* a = &acc[(zo * JCO + j) * 4];
                    r.x = a[0]; r.y = a[1]; r.z = a[2]; r.w = a[3];
                    if (relu) {
                        r.x = fmaxf(r.x, 0.f); r.y = fmaxf(r.y, 0.f);
                        r.z = fmaxf(r.z, 0.f); r.w = fmaxf(r.w, 0.f);
                    }
                    *(float4*)(out + ((size_t)n * Cout + co) * vox +
                               ((size_t)z * D + yo) * D + x0) = r;
                }
            }
        }
    }
}

// ---------------------------------------------------------------------------
// Fallback direct conv for tiny volumes (D < 16).
// ---------------------------------------------------------------------------
__global__ void conv3x3x3(const float* __restrict__ in, const float* __restrict__ w,
                          const float* __restrict__ bias, float* __restrict__ out,
                          int Cin, int D, int do_relu) {
    const int vox = D * D * D;
    const int co = blockIdx.y;
    const int n  = blockIdx.z;
    extern __shared__ float ws[];
    const int nw = Cin * 27;
    for (int i = threadIdx.x; i < nw; i += blockDim.x)
        ws[i] = w[(size_t)co * nw + i];
    __syncthreads();

    int idx = blockIdx.x * blockDim.x + threadIdx.x;
    if (idx >= vox) return;
    int x = idx % D;
    int t = idx / D;
    int y = t % D;
    int z = t / D;

    const float* inb = in + (size_t)n * Cin * vox;
    float acc = bias[co];
    for (int ci = 0; ci < Cin; ci++) {
        const float* ip = inb + (size_t)ci * vox;
        const float* wp = ws + ci * 27;
        #pragma unroll
        for (int kz = 0; kz < 3; kz++) {
            int zz = z + kz - 1;
            if ((unsigned)zz >= (unsigned)D) continue;
            #pragma unroll
            for (int ky = 0; ky < 3; ky++) {
                int yy = y + ky - 1;
                if ((unsigned)yy >= (unsigned)D) continue;
                const float* row = ip + ((size_t)zz * D + yy) * D;
                #pragma unroll
                for (int kx = 0; kx < 3; kx++) {
                    int xx = x + kx - 1;
                    if ((unsigned)xx >= (unsigned)D) continue;
                    acc += row[xx] * wp[kz * 9 + ky * 3 + kx];
                }
            }
        }
    }
    if (do_relu) acc = fmaxf(acc, 0.f);
    out[((size_t)n * gridDim.y + co) * vox + idx] = acc;
}

// ---------------------------------------------------------------------------
__global__ void inorm_stats(const float* __restrict__ in, float* __restrict__ mu,
                            float* __restrict__ rsig, int vox) {
    const int nc = blockIdx.x;
    const float4* p = (const float4*)(in + (size_t)nc * vox);
    int n4 = vox >> 2;
    float s = 0.f, s2 = 0.f;
    for (int i = threadIdx.x; i < n4; i += 256) {
        float4 v = p[i];
        s  += v.x + v.y + v.z + v.w;
        s2 += v.x * v.x + v.y * v.y + v.z * v.z + v.w * v.w;
    }
    __shared__ float sh[256], sh2[256];
    sh[threadIdx.x] = s;
    sh2[threadIdx.x] = s2;
    __syncthreads();
    for (int o = 128; o > 0; o >>= 1) {
        if (threadIdx.x < o) {
            sh[threadIdx.x]  += sh[threadIdx.x + o];
            sh2[threadIdx.x] += sh2[threadIdx.x + o];
        }
        __syncthreads();
    }
    if (threadIdx.x == 0) {
        float m = sh[0] / (float)vox;
        float var = sh2[0] / (float)vox - m * m;
        mu[nc] = m;
        rsig[nc] = rsqrtf(var + 1e-5f);
    }
}

__global__ void norm_prelu(float* __restrict__ data, const float* __restrict__ mu,
                           const float* __restrict__ rsig, const float* __restrict__ alpha,
                           int vox) {
    int nc = blockIdx.y;
    int i = (blockIdx.x * 256 + threadIdx.x) << 2;
    if (i >= vox) return;
    float m = mu[nc], rs = rsig[nc], a = *alpha;
    float4* p = (float4*)(data + (size_t)nc * vox + i);
    float4 v = *p;
    v.x = (v.x - m) * rs; v.x = v.x >= 0.f ? v.x : a * v.x;
    v.y = (v.y - m) * rs; v.y = v.y >= 0.f ? v.y : a * v.y;
    v.z = (v.z - m) * rs; v.z = v.z >= 0.f ? v.z : a * v.z;
    v.w = (v.w - m) * rs; v.w = v.w >= 0.f ? v.w : a * v.w;
    *p = v;
}

// ---------------------------------------------------------------------------
__global__ void resize_tri(const float* __restrict__ in, float* __restrict__ out,
                           int C, int inD, int outD, float gain) {
    const int ov = outD * outD * outD;
    const int iv = inD * inD * inD;
    int idx = blockIdx.x * blockDim.x + threadIdx.x;
    int total = C * ov;
    if (idx >= total) return;
    int p = idx % ov;
    int c = idx / ov;
    int x = p % outD;
    int t = p / outD;
    int y = t % outD;
    int z = t / outD;

    float r = (float)(inD - 1) / (float)(outD - 1);
    float cz = z * r, cy = y * r, cx = x * r;
    int z0 = min(max((int)floorf(cz), 0), inD - 2);
    int y0 = min(max((int)floorf(cy), 0), inD - 2);
    int x0 = min(max((int)floorf(cx), 0), inD - 2);
    float tz = cz - (float)z0;
    float ty = cy - (float)y0;
    float tx = cx - (float)x0;

    const float* ip = in + (size_t)c * iv;
    size_t b000 = ((size_t)z0 * inD + y0) * inD + x0;
    size_t sy = inD, sz = (size_t)inD * inD;
    float v000 = ip[b000],           v001 = ip[b000 + 1];
    float v010 = ip[b000 + sy],      v011 = ip[b000 + sy + 1];
    float v100 = ip[b000 + sz],      v101 = ip[b000 + sz + 1];
    float v110 = ip[b000 + sz + sy], v111 = ip[b000 + sz + sy + 1];

    float c00 = v000 * (1.f - tx) + v001 * tx;
    float c01 = v010 * (1.f - tx) + v011 * tx;
    float c10 = v100 * (1.f - tx) + v101 * tx;
    float c11 = v110 * (1.f - tx) + v111 * tx;
    float c0 = c00 * (1.f - ty) + c01 * ty;
    float c1 = c10 * (1.f - ty) + c11 * ty;
    out[idx] = gain * (c0 * (1.f - tz) + c1 * tz);
}

// ---------------------------------------------------------------------------
// Tap computation shared by all grid-sample kernels (zero-padding semantics).
// ---------------------------------------------------------------------------
__device__ __forceinline__ void calc_taps(float fz, float fy, float fx,
                                          int z, int y, int x, int D,
                                          int* offs, float* wts) {
    float zz = (float)z + fz;
    float yy = (float)y + fy;
    float xx = (float)x + fx;
    float zf = floorf(zz), yf = floorf(yy), xf = floorf(xx);
    int z0 = (int)zf, y0 = (int)yf, x0 = (int)xf;
    float wz = zz - zf, wy = yy - yf, wx = xx - xf;
    int k = 0;
    #pragma unroll
    for (int dz = 0; dz < 2; dz++) {
        int zi = z0 + dz;
        bool vz = (zi >= 0) && (zi < D);
        int zc = min(max(zi, 0), D - 1);
        float gz = dz ? wz : 1.f - wz;
        #pragma unroll
        for (int dy = 0; dy < 2; dy++) {
            int yi = y0 + dy;
            bool vy = (yi >= 0) && (yi < D);
            int yc = min(max(yi, 0), D - 1);
            float gy = dy ? wy : 1.f - wy;
            #pragma unroll
            for (int dx = 0; dx < 2; dx++) {
                int xi = x0 + dx;
                bool vx = (xi >= 0) && (xi < D);
                int xc = min(max(xi, 0), D - 1);
                float gx = dx ? wx : 1.f - wx;
                offs[k] = (zc * D + yc) * D + xc;
                wts[k] = (vz && vy && vx) ? gz * gy * gx : 0.f;
                k++;
            }
        }
    }
}

// Generic warp: out[c,p] = (addend?addend[c,p]:0) + sample(src[c], grid+flow).
__global__ void warp_generic(const float* __restrict__ src, const float* __restrict__ flow,
                             const float* __restrict__ addend, float* __restrict__ out,
                             int C, int D) {
    const int vox = D * D * D;
    int idx = blockIdx.x * blockDim.x + threadIdx.x;
    if (idx >= vox) return;
    int x = idx % D;
    int t = idx / D;
    int y = t % D;
    int z = t / D;

    int offs[8];
    float wts[8];
    calc_taps(flow[idx], flow[vox + idx], flow[2 * vox + idx], z, y, x, D, offs, wts);

    for (int c = 0; c < C; c++) {
        const float* sp = src + (size_t)c * vox;
        float acc = addend ? addend[(size_t)c * vox + idx] : 0.f;
        #pragma unroll
        for (int j = 0; j < 8; j++)
            acc += sp[offs[j]] * wts[j];
        out[(size_t)c * vox + idx] = acc;
    }
}

// Fused: xw = (up ? warp(xi, up) : xi); cat = [yi+xw, yi-xw].
__global__ void warp_cat(const float* __restrict__ xi, const float* __restrict__ yi,
                         const float* __restrict__ up, float* __restrict__ cat, int D) {
    const int vox = D * D * D;
    int idx = blockIdx.x * blockDim.x + threadIdx.x;
    if (idx >= vox) return;

    int offs[8];
    float wts[8];
    bool w = (up != nullptr);
    if (w) {
        int x = idx % D;
        int t = idx / D;
        int y = t % D;
        int z = t / D;
        calc_taps(up[idx], up[vox + idx], up[2 * vox + idx], z, y, x, D, offs, wts);
    }
    for (int c = 0; c < 16; c++) {
        const float* sp = xi + (size_t)c * vox;
        float xw;
        if (w) {
            xw = 0.f;
            #pragma unroll
            for (int j = 0; j < 8; j++) xw += sp[offs[j]] * wts[j];
        } else {
            xw = sp[idx];
        }
        float b = yi[(size_t)c * vox + idx];
        cat[(size_t)c * vox + idx] = b + xw;
        cat[(size_t)(16 + c) * vox + idx] = b - xw;
    }
}

// ---------------------------------------------------------------------------
// Fused vecint for small levels (single block!). bufA <- flow*scale, then
// `steps` squaring iterations ping-ponging bufA/bufB with in-kernel syncs,
// then optional composition with up (in place on the current buffer).
// Result buffer parity: steps odd -> bufB, even -> bufA.
// ---------------------------------------------------------------------------
__global__ void vecint_small(const float* __restrict__ flow, const float* __restrict__ up,
                             float* __restrict__ bufA, float* __restrict__ bufB,
                             int D, float scale, int steps) {
    const int vox = D * D * D;
    const int T = blockDim.x;
    const int tid = threadIdx.x;

    for (int i = tid; i < 3 * vox; i += T) bufA[i] = flow[i] * scale;
    __syncthreads();

    float* cur = bufA;
    float* nxt = bufB;
    for (int s = 0; s < steps; s++) {
        for (int idx = tid; idx < vox; idx += T) {
            int x = idx % D;
            int t = idx / D;
            int y = t % D;
            int z = t / D;
            int offs[8];
            float wts[8];
            calc_taps(cur[idx], cur[vox + idx], cur[2 * vox + idx], z, y, x, D,
                      offs, wts);
            #pragma unroll
            for (int c = 0; c < 3; c++) {
                const float* sp = cur + c * vox;
                float acc = sp[idx];
                #pragma unroll
                for (int j = 0; j < 8; j++) acc += sp[offs[j]] * wts[j];
                nxt[c * vox + idx] = acc;
            }
        }
        __syncthreads();
        float* tmp = cur; cur = nxt; nxt = tmp;
    }

    if (up) {
        for (int idx = tid; idx < vox; idx += T) {
            int x = idx % D;
            int t = idx / D;
            int y = t % D;
            int z = t / D;
            int offs[8];
            float wts[8];
            calc_taps(cur[idx], cur[vox + idx], cur[2 * vox + idx], z, y, x, D,
                      offs, wts);
            #pragma unroll
            for (int c = 0; c < 3; c++) {
                const float* sp = up + c * vox;
                float acc = 0.f;
                #pragma unroll
                for (int j = 0; j < 8; j++) acc += sp[offs[j]] * wts[j];
                cur[c * vox + idx] += acc;   // in place: gathers read up only
            }
        }
    }
}

__global__ void scale_k(const float* __restrict__ in, float* __restrict__ out,
                        float s, int n) {
    int i = (blockIdx.x * blockDim.x + threadIdx.x) << 2;
    if (i >= n) return;
    float4 v = *(const float4*)(in + i);
    v.x *= s; v.y *= s; v.z *= s; v.w *= s;
    *(float4*)(out + i) = v;
}

// ---------------------------------------------------------------------------
struct Ptrs {
    float *bufA, *bufB, *xs, *ys, *cat, *feat1, *feat2;
    float *flow, *vecA, *vecB, *up, *mu, *rsig, *wrep;
};
static Ptrs P;
static bool g_inited = false;

static void init_ptrs() {
    cudaGetSymbolAddress((void**)&P.bufA, g_bufA);
    cudaGetSymbolAddress((void**)&P.bufB, g_bufB);
    cudaGetSymbolAddress((void**)&P.xs, g_xs);
    cudaGetSymbolAddress((void**)&P.ys, g_ys);
    cudaGetSymbolAddress((void**)&P.cat, g_cat);
    cudaGetSymbolAddress((void**)&P.feat1, g_feat1);
    cudaGetSymbolAddress((void**)&P.feat2, g_feat2);
    cudaGetSymbolAddress((void**)&P.flow, g_flow);
    cudaGetSymbolAddress((void**)&P.vecA, g_vecA);
    cudaGetSymbolAddress((void**)&P.vecB, g_vecB);
    cudaGetSymbolAddress((void**)&P.up, g_up);
    cudaGetSymbolAddress((void**)&P.mu, g_mu);
    cudaGetSymbolAddress((void**)&P.rsig, g_rsig);
    cudaGetSymbolAddress((void**)&P.wrep, g_wrepAll);
}

// host mirror of the repack table
struct RInfo { int cin, cout, cop, off; };
static const RInfo RI[12] = {
    {1,16,16,0}, {16,32,32,432}, {32,16,16,14256},
    {32,32,32,28080}, {32,27,32,55728}, {27,3,4,83376},
    {32,32,32,86292}, {32,27,32,113940}, {27,3,4,141588},
    {32,32,32,144504}, {32,27,32,172152}, {27,3,4,199800},
};

static void launch_conv_t(int id, const float* in, const float* b, float* outp,
                          int D, int relu, int N) {
    const RInfo& r = RI[id];
    int JCO = (r.cout >= 8) ? 4 : 1;
    int W = 4 * JCO;
    int gy = (r.cout + W - 1) / W;
    int tilesX = (D + 31) / 32;
    int tilesY = D / 4;
    int tilesZ = D / 4;
    dim3 grid(tilesX * tilesY * tilesZ, gy, N);
    const float* wr = P.wrep + r.off;
    if (JCO == 4)
        conv_tiled3<4><<<grid, 128>>>(in, wr, b, outp, r.cin, r.cout, r.cop, D,
                                      relu, tilesX, tilesY);
    else
        conv_tiled3<1><<<grid, 128>>>(in, wr, b, outp, r.cin, r.cout, r.cop, D,
                                      relu, tilesX, tilesY);
}

extern "C" void kernel_launch(void* const* d_in, const int* in_sizes, int n_in,
                              void* d_out, int out_size) {
    (void)in_sizes; (void)n_in; (void)out_size;
    if (!g_inited) { init_ptrs(); g_inited = true; }

    const float* x      = (const float*)d_in[0];
    const float* y      = (const float*)d_in[1];
    const float* enc_w1 = (const float*)d_in[2];
    const float* enc_b1 = (const float*)d_in[3];
    const float* enc_w2 = (const float*)d_in[4];
    const float* enc_b2 = (const float*)d_in[5];
    const float* enc_w3 = (const float*)d_in[6];
    const float* enc_b3 = (const float*)d_in[7];
    const float* prelu1 = (const float*)d_in[8];
    const float* prelu2 = (const float*)d_in[9];
    const float* prelu3 = (const float*)d_in[10];
    const float* dw_w1  = (const float*)d_in[11];
    const float* dw_b1  = (const float*)d_in[12];
    const float* dw_w2  = (const float*)d_in[13];
    const float* dw_b2  = (const float*)d_in[14];
    const float* dw_w3  = (const float*)d_in[15];
    const float* dw_b3  = (const float*)d_in[16];
    float* out = (float*)d_out;

    const int TB = 256;

    // one repack kernel for all tiled convs
    repack_all<<<dim3(108, 12), 256>>>(enc_w1, enc_w2, enc_w3,
                                       dw_w1, dw_w2, dw_w3, P.wrep);

    // ---------------- encoder (batch 2: [x;y]) ----------------
    cudaMemcpyAsync(P.bufA, x, (size_t)V64 * 4, cudaMemcpyDeviceToDevice);
    cudaMemcpyAsync(P.bufA + V64, y, (size_t)V64 * 4, cudaMemcpyDeviceToDevice);

    launch_conv_t(0, P.bufA, enc_b1, P.bufB, 64, 0, 2);
    inorm_stats<<<32, 256>>>(P.bufB, P.mu, P.rsig, V64);
    norm_prelu<<<dim3(V64 / 1024, 32), 256>>>(P.bufB, P.mu, P.rsig, prelu1, V64);
    launch_conv_t(1, P.bufB, enc_b2, P.bufA, 64, 0, 2);
    inorm_stats<<<64, 256>>>(P.bufA, P.mu, P.rsig, V64);
    norm_prelu<<<dim3(V64 / 1024, 64), 256>>>(P.bufA, P.mu, P.rsig, prelu2, V64);
    launch_conv_t(2, P.bufA, enc_b3, P.bufB, 64, 0, 2);
    inorm_stats<<<32, 256>>>(P.bufB, P.mu, P.rsig, V64);
    norm_prelu<<<dim3(V64 / 1024, 32), 256>>>(P.bufB, P.mu, P.rsig, prelu3, V64);

    // pyramid: level 0 aliases encoder output (bufB), levels 1..4 in xs/ys
    static const int OFF[5] = {0, 262144, 294912, 299008, 299520};
    const float* xs_lv[5];
    const float* ys_lv[5];
    xs_lv[0] = P.bufB;
    ys_lv[0] = P.bufB + (size_t)16 * V64;
    for (int i = 1; i < 5; i++) {
        xs_lv[i] = P.xs + (size_t)16 * OFF[i];
        ys_lv[i] = P.ys + (size_t)16 * OFF[i];
    }
    for (int i = 1; i < 5; i++) {
        int inD = 64 >> (i - 1), outD = 64 >> i;
        int total = 16 * outD * outD * outD;
        resize_tri<<<(total + TB - 1) / TB, TB>>>(xs_lv[i - 1], (float*)xs_lv[i],
                                                  16, inD, outD, 1.f);
        resize_tri<<<(total + TB - 1) / TB, TB>>>(ys_lv[i - 1], (float*)ys_lv[i],
                                                  16, inD, outD, 1.f);
    }

    static const size_t int_off[5] = {0, 786432, 884736, 897024, 898560};
    const size_t pos_base = 898752;

    for (int L = 4; L >= 0; L--) {
        int s = 64 >> L;
        int vox = s * s * s;
        int sb = (vox + TB - 1) / TB;
        const float* up = (L < 4) ? P.up : nullptr;

        // fused (optional warp) + concat
        warp_cat<<<sb, TB>>>(xs_lv[L], ys_lv[L], up, P.cat, s);

        // conv chain
        if (s >= 16) {
            launch_conv_t(3 + L * 3 + 0, P.cat,   dw_b1 + (size_t)L * 32, P.feat1, s, 1, 1);
            launch_conv_t(3 + L * 3 + 1, P.feat1, dw_b2 + (size_t)L * 27, P.feat2, s, 1, 1);
            launch_conv_t(3 + L * 3 + 2, P.feat2, dw_b3 + (size_t)L * 3,  P.flow,  s, 0, 1);
        } else {
            conv3x3x3<<<dim3(sb, 32, 1), TB, 32 * 27 * 4>>>(
                P.cat, dw_w1 + (size_t)L * 32 * 32 * 27, dw_b1 + (size_t)L * 32,
                P.feat1, 32, s, 1);
            conv3x3x3<<<dim3(sb, 27, 1), TB, 32 * 27 * 4>>>(
                P.feat1, dw_w2 + (size_t)L * 27 * 32 * 27, dw_b2 + (size_t)L * 27,
                P.feat2, 32, s, 1);
            conv3x3x3<<<dim3(sb, 3, 1), TB, 27 * 27 * 4>>>(
                P.feat2, dw_w3 + (size_t)L * 3 * 27 * 27, dw_b3 + (size_t)L * 3,
                P.flow, 27, s, 0);
        }

        cudaMemcpyAsync(out + int_off[L], P.flow, (size_t)3 * vox * 4,
                        cudaMemcpyDeviceToDevice);

        float* result;
        if (s <= 16) {
            // fused single-block vecint + compose; 7 steps (odd) -> vecB
            vecint_small<<<1, 1024>>>(P.flow, up, P.vecA, P.vecB, s, 1.f / 128.f, 7);
            result = P.vecB;
        } else {
            scale_k<<<(3 * vox / 4 + TB - 1) / TB, TB>>>(P.flow, P.vecA,
                                                         1.f / 128.f, 3 * vox);
            float* va = P.vecA;
            float* vb = P.vecB;
            for (int step = 0; step < 7; step++) {
                warp_generic<<<sb, TB>>>(va, va, va, vb, 3, s);
                float* tmp = va; va = vb; vb = tmp;
            }
            if (L < 4) {
                warp_generic<<<sb, TB>>>(P.up, va, va, va, 3, s);
            }
            result = va;
        }

        cudaMemcpyAsync(out + pos_base + int_off[L], result, (size_t)3 * vox * 4,
                        cudaMemcpyDeviceToDevice);

        if (L > 0) {
            int outD = 2 * s;
            int total = 3 * outD * outD * outD;
            resize_tri<<<(total + TB - 1) / TB, TB>>>(result, P.up, 3, s, outD, 2.f);
        }
    }
}